// round 4
// baseline (speedup 1.0000x reference)
#include <cuda_runtime.h>
#include <math.h>

#define Bsz   128
#define Wd    128
#define FIN   64
#define NN    64
#define EE    4096
#define EDd   16
#define HC    128
#define FLATd 8192
#define HIDd  2048
#define SPLITK 16
#define CHUNK 128

// ---------------- scratch ----------------
__device__ __align__(128) float g_xg[Bsz * NN * Wd];
__device__ __align__(128) float g_h[Bsz * NN * HC];
__device__ __align__(128) float g_xflat[Bsz * FLATd];
__device__ __align__(128) float g_h1part[SPLITK * Bsz * HIDd];
__device__ __align__(128) float g_h1[Bsz * HIDd];
__device__ int  g_csr_off[NN + 1];
__device__ int2 g_csr_es[EE];

// ---------------- f32x2 helpers ----------------
__device__ __forceinline__ unsigned long long pk2(float lo, float hi) {
    unsigned long long r;
    asm("mov.b64 %0, {%1,%2};" : "=l"(r) : "f"(lo), "f"(hi));
    return r;
}
__device__ __forceinline__ void fma2(unsigned long long& d,
                                     unsigned long long a, unsigned long long b) {
    asm("fma.rn.f32x2 %0, %1, %2, %0;" : "+l"(d) : "l"(a), "l"(b));
}
__device__ __forceinline__ float2 upk2(unsigned long long v) {
    float2 r;
    asm("mov.b64 {%0,%1}, %2;" : "=f"(r.x), "=f"(r.y) : "l"(v));
    return r;
}

// ---------------- CSR build ----------------
__global__ void k_csr(const int* __restrict__ ei) {
    __shared__ int cnt[NN];
    __shared__ int off[NN + 1];
    __shared__ int cur[NN];
    int tid = threadIdx.x;
    if (tid < NN) cnt[tid] = 0;
    __syncthreads();
    for (int e = tid; e < EE; e += blockDim.x)
        atomicAdd(&cnt[ei[EE + e]], 1);
    __syncthreads();
    if (tid == 0) {
        int run = 0;
        for (int k = 0; k < NN; k++) { off[k] = run; cur[k] = run; run += cnt[k]; }
        off[NN] = run;
    }
    __syncthreads();
    for (int e = tid; e < EE; e += blockDim.x) {
        int d = ei[EE + e];
        int pos = atomicAdd(&cur[d], 1);
        g_csr_es[pos] = make_int2(e, ei[e]);
    }
    if (tid <= NN) g_csr_off[tid] = off[tid];
}

// ---------------- TCN conv1d(k=3,pad=1) ----------------
__global__ void k_tcn(const float* __restrict__ x,
                      const float* __restrict__ tw,
                      const float* __restrict__ tb) {
    __shared__ float xs[FIN * 129];
    __shared__ float sw[16 * 192];
    int b = blockIdx.y, nc = blockIdx.x;
    int tid = threadIdx.x;
    const float* xb = x + (size_t)b * Wd * FIN;
    for (int idx = tid; idx < Wd * FIN; idx += 128) {
        int w = idx >> 6, i = idx & 63;
        xs[i * 129 + w] = xb[idx];
    }
    for (int idx = tid; idx < 16 * 192; idx += 128)
        sw[idx] = tw[nc * 16 * 192 + idx];
    __syncthreads();
    int w = tid;
    float acc[16];
#pragma unroll
    for (int nl = 0; nl < 16; nl++) acc[nl] = tb[nc * 16 + nl];
    for (int i = 0; i < FIN; i++) {
        float x0 = xs[i * 129 + w];
        float xm = (w > 0)   ? xs[i * 129 + w - 1] : 0.f;
        float xp = (w < 127) ? xs[i * 129 + w + 1] : 0.f;
#pragma unroll
        for (int nl = 0; nl < 16; nl++) {
            const float* wp = &sw[nl * 192 + i * 3];
            acc[nl] += xm * wp[0] + x0 * wp[1] + xp * wp[2];
        }
    }
#pragma unroll
    for (int nl = 0; nl < 16; nl++)
        g_xg[((size_t)b * NN + nc * 16 + nl) * Wd + w] = acc[nl];
}

// ---------------- lin_l projection ----------------
__global__ void k_linl(const float* __restrict__ lw, const float* __restrict__ lb) {
    __shared__ float xs[NN * 129];
    __shared__ float ws[64 * 33];
    int b = blockIdx.y, oc = blockIdx.x;
    int tid = threadIdx.x;
    for (int idx = tid; idx < NN * Wd; idx += 256) {
        int n = idx >> 7, w = idx & 127;
        xs[n * 129 + w] = g_xg[(size_t)b * NN * Wd + idx];
    }
    int tx = tid & 15, ty = tid >> 4;
    float acc[4][4];
#pragma unroll
    for (int i = 0; i < 4; i++)
#pragma unroll
        for (int j = 0; j < 4; j++) acc[i][j] = 0.f;
    for (int wc = 0; wc < 4; wc++) {
        __syncthreads();
        for (int idx = tid; idx < 64 * 32; idx += 256) {
            int ol = idx >> 5, wl = idx & 31;
            ws[ol * 33 + wl] = lw[(oc * 64 + ol) * Wd + wc * 32 + wl];
        }
        __syncthreads();
#pragma unroll 4
        for (int wl = 0; wl < 32; wl++) {
            float a[4], bb[4];
#pragma unroll
            for (int j = 0; j < 4; j++) a[j]  = xs[(ty * 4 + j) * 129 + wc * 32 + wl];
#pragma unroll
            for (int j = 0; j < 4; j++) bb[j] = ws[(tx * 4 + j) * 33 + wl];
#pragma unroll
            for (int i = 0; i < 4; i++)
#pragma unroll
                for (int j = 0; j < 4; j++) acc[i][j] += a[i] * bb[j];
        }
    }
#pragma unroll
    for (int i = 0; i < 4; i++)
#pragma unroll
        for (int j = 0; j < 4; j++) {
            int n = ty * 4 + i, o = oc * 64 + tx * 4 + j;
            g_h[((size_t)b * NN + n) * HC + o] = acc[i][j] + lb[o];
        }
}

// ---- segmented 16-value warp reduce: p[j] per lane -> sum over lanes.
// Returns v such that lanes 2e and 2e+1 hold the total for edge e (e=0..15).
__device__ __forceinline__ float reduce16(float p[16], int lane) {
    // offset 16: keep upper 8 if lane bit4
    {
        bool hi = (lane & 16);
#pragma unroll
        for (int j = 0; j < 8; j++) {
            float snd = hi ? p[j] : p[j + 8];
            float rcv = __shfl_xor_sync(0xffffffffu, snd, 16);
            p[j] = (hi ? p[j + 8] : p[j]) + rcv;
        }
    }
    {
        bool hi = (lane & 8);
#pragma unroll
        for (int j = 0; j < 4; j++) {
            float snd = hi ? p[j] : p[j + 4];
            float rcv = __shfl_xor_sync(0xffffffffu, snd, 8);
            p[j] = (hi ? p[j + 4] : p[j]) + rcv;
        }
    }
    {
        bool hi = (lane & 4);
#pragma unroll
        for (int j = 0; j < 2; j++) {
            float snd = hi ? p[j] : p[j + 2];
            float rcv = __shfl_xor_sync(0xffffffffu, snd, 4);
            p[j] = (hi ? p[j + 2] : p[j]) + rcv;
        }
    }
    {
        bool hi = (lane & 2);
        float snd = hi ? p[0] : p[1];
        float rcv = __shfl_xor_sync(0xffffffffu, snd, 2);
        p[0] = (hi ? p[1] : p[0]) + rcv;
    }
    return p[0] + __shfl_xor_sync(0xffffffffu, p[0], 1);
}

// ---------------- GAT: chunked deferred softmax + batched reductions ----------------
__global__ void __launch_bounds__(128) k_gat(const float* __restrict__ eattr,
                      const float* __restrict__ lew,
                      const float* __restrict__ leb,
                      const float* __restrict__ att) {
    __shared__ float4 ea_s[CHUNK * 4];
    __shared__ int    src_s[CHUNK];
    __shared__ int    eid_s[CHUNK];
    int n = blockIdx.x, b = blockIdx.y;
    int t = threadIdx.x;
    int lane = t & 31;
    const float4* w4 = (const float4*)(lew + t * EDd);
    float4 w0 = w4[0], w1 = w4[1], w2 = w4[2], w3 = w4[3];
    float att_t = att[t];
    const float* hb = g_h + (size_t)b * NN * HC;
    float ebhd = leb[t] + hb[n * HC + t];

    int beg = g_csr_off[n], end = g_csr_off[n + 1];
    int deg = end - beg;
    const int2* lst = g_csr_es + beg;
    const float4* eab = (const float4*)eattr + (size_t)b * EE * 4;

    float m = -1e30f, den = 0.f, acc = 0.f;

    for (int base = 0; base < deg; base += CHUNK) {
        int cnt = min(CHUNK, deg - base);
        if (t < cnt) {
            int2 p = lst[base + t];
            eid_s[t] = p.x; src_s[t] = p.y;
        } else {
            eid_s[t] = 0; src_s[t] = 0;
        }
        __syncthreads();
        for (int idx = t; idx < cnt * 4; idx += 128)
            ea_s[idx] = eab[(size_t)eid_s[idx >> 2] * 4 + (idx & 3)];
        __syncthreads();

        // ---- pass 1: scores, 32-edge windows, batched reduce ----
        float sr[4];
#pragma unroll
        for (int q = 0; q < 4; q++) {
            int win = q * 32;
            float vA, vB;
            {
                float p[16];
#pragma unroll
                for (int j = 0; j < 16; j++) {
                    int e = win + j;
                    float4 q0 = ea_s[e * 4 + 0];
                    float4 q1 = ea_s[e * 4 + 1];
                    float4 q2 = ea_s[e * 4 + 2];
                    float4 q3 = ea_s[e * 4 + 3];
                    float hs = hb[src_s[e] * HC + t];
                    float z = ebhd + hs
                        + q0.x * w0.x + q0.y * w0.y + q0.z * w0.z + q0.w * w0.w
                        + q1.x * w1.x + q1.y * w1.y + q1.z * w1.z + q1.w * w1.w
                        + q2.x * w2.x + q2.y * w2.y + q2.z * w2.z + q2.w * w2.w
                        + q3.x * w3.x + q3.y * w3.y + q3.z * w3.z + q3.w * w3.w;
                    p[j] = fmaxf(z, 0.01f * z) * att_t;
                }
                vA = reduce16(p, lane);
            }
            {
                float p[16];
#pragma unroll
                for (int j = 0; j < 16; j++) {
                    int e = win + 16 + j;
                    float4 q0 = ea_s[e * 4 + 0];
                    float4 q1 = ea_s[e * 4 + 1];
                    float4 q2 = ea_s[e * 4 + 2];
                    float4 q3 = ea_s[e * 4 + 3];
                    float hs = hb[src_s[e] * HC + t];
                    float z = ebhd + hs
                        + q0.x * w0.x + q0.y * w0.y + q0.z * w0.z + q0.w * w0.w
                        + q1.x * w1.x + q1.y * w1.y + q1.z * w1.z + q1.w * w1.w
                        + q2.x * w2.x + q2.y * w2.y + q2.z * w2.z + q2.w * w2.w
                        + q3.x * w3.x + q3.y * w3.y + q3.z * w3.z + q3.w * w3.w;
                    p[j] = fmaxf(z, 0.01f * z) * att_t;
                }
                vB = reduce16(p, lane);
            }
            int idx2 = 2 * (lane & 15);
            float s0 = __shfl_sync(0xffffffffu, vA, idx2);
            float s1 = __shfl_sync(0xffffffffu, vB, idx2);
            float sv = (lane & 16) ? s1 : s0;          // lane l holds edge win+l
            sr[q] = (win + lane < cnt) ? sv : -1e30f;  // mask padding
        }

        // ---- pass 2: chunk max / weights / denom ----
        float cm = fmaxf(fmaxf(sr[0], sr[1]), fmaxf(sr[2], sr[3]));
        cm = fmaxf(cm, __shfl_xor_sync(0xffffffffu, cm, 16));
        cm = fmaxf(cm, __shfl_xor_sync(0xffffffffu, cm, 8));
        cm = fmaxf(cm, __shfl_xor_sync(0xffffffffu, cm, 4));
        cm = fmaxf(cm, __shfl_xor_sync(0xffffffffu, cm, 2));
        cm = fmaxf(cm, __shfl_xor_sync(0xffffffffu, cm, 1));
        float mnew = fmaxf(m, cm);
        float resc = __expf(m - mnew);
        den *= resc; acc *= resc;
        m = mnew;
        float wr[4];
#pragma unroll
        for (int q = 0; q < 4; q++) wr[q] = __expf(sr[q] - m);
        float dl = wr[0] + wr[1] + wr[2] + wr[3];
        dl += __shfl_xor_sync(0xffffffffu, dl, 16);
        dl += __shfl_xor_sync(0xffffffffu, dl, 8);
        dl += __shfl_xor_sync(0xffffffffu, dl, 4);
        dl += __shfl_xor_sync(0xffffffffu, dl, 2);
        dl += __shfl_xor_sync(0xffffffffu, dl, 1);
        den += dl;

        // ---- pass 3: aggregation ----
#pragma unroll
        for (int q = 0; q < 4; q++) {
            int lim = min(32, cnt - q * 32);
            for (int jj = 0; jj < lim; jj++) {
                float wj = __shfl_sync(0xffffffffu, wr[q], jj);
                float hs = hb[src_s[q * 32 + jj] * HC + t];
                acc += wj * hs;
            }
        }
        __syncthreads();
    }

    float v = acc / (den + 1e-16f);
    float o = (v > 0.f) ? v : expm1f(v);
    g_xflat[(size_t)b * FLATd + n * HC + t] = o;
}

// ---------------- fc1: 128m x 128n x 512k per block, FFMA2 zero-MOV ----------------
__global__ void __launch_bounds__(256) k_fc1(const float* __restrict__ wq) {
    __shared__ float sA[2][16 * 128];    // [k][m]
    __shared__ float sBd[2][16 * 256];   // [k][2n] duplicated pairs
    int ntile = blockIdx.x << 7;
    int k0 = blockIdx.y << 9;
    int tid = threadIdx.x;
    int row = tid & 127, koff = (tid >> 7) << 3;
    int tx = tid & 15, ty = tid >> 4;

    const float* Ap = g_xflat + (size_t)row * FLATd + k0 + koff;
    const float* Bp = wq + (size_t)(ntile + row) * FLATd + k0 + koff;

    unsigned long long acc2[4][8];
#pragma unroll
    for (int i = 0; i < 4; i++)
#pragma unroll
        for (int j = 0; j < 8; j++) acc2[i][j] = 0ull;

    float4 a0 = *(const float4*)Ap;
    float4 a1 = *(const float4*)(Ap + 4);
    float4 b0 = *(const float4*)Bp;
    float4 b1 = *(const float4*)(Bp + 4);
    {
        float av[8] = {a0.x,a0.y,a0.z,a0.w,a1.x,a1.y,a1.z,a1.w};
        float bv[8] = {b0.x,b0.y,b0.z,b0.w,b1.x,b1.y,b1.z,b1.w};
#pragma unroll
        for (int i = 0; i < 8; i++) {
            sA[0][(koff + i) * 128 + row] = av[i];
            *(unsigned long long*)&sBd[0][(koff + i) * 256 + row * 2] = pk2(bv[i], bv[i]);
        }
    }
    __syncthreads();

    for (int kt = 0; kt < 32; kt++) {
        int cur = kt & 1;
        if (kt < 31) {
            Ap += 16; Bp += 16;
            a0 = *(const float4*)Ap;
            a1 = *(const float4*)(Ap + 4);
            b0 = *(const float4*)Bp;
            b1 = *(const float4*)(Bp + 4);
        }
#pragma unroll
        for (int kk = 0; kk < 16; kk++) {
            unsigned long long aa[4];
#pragma unroll
            for (int i = 0; i < 4; i++)
                aa[i] = *(const unsigned long long*)&sA[cur][kk * 128 + i * 32 + ty * 2];
            unsigned long long bb[8];
#pragma unroll
            for (int j = 0; j < 4; j++) {
                ulonglong2 bv = *(const ulonglong2*)&sBd[cur][kk * 256 + j * 64 + tx * 4];
                bb[2 * j] = bv.x; bb[2 * j + 1] = bv.y;
            }
#pragma unroll
            for (int i = 0; i < 4; i++)
#pragma unroll
                for (int j = 0; j < 8; j++)
                    fma2(acc2[i][j], aa[i], bb[j]);
        }
        if (kt < 31) {
            int nxt = cur ^ 1;
            float av[8] = {a0.x,a0.y,a0.z,a0.w,a1.x,a1.y,a1.z,a1.w};
            float bv[8] = {b0.x,b0.y,b0.z,b0.w,b1.x,b1.y,b1.z,b1.w};
#pragma unroll
            for (int i = 0; i < 8; i++) {
                sA[nxt][(koff + i) * 128 + row] = av[i];
                *(unsigned long long*)&sBd[nxt][(koff + i) * 256 + row * 2] = pk2(bv[i], bv[i]);
            }
        }
        __syncthreads();
    }

    float* outp = g_h1part + (size_t)blockIdx.y * (Bsz * HIDd);
#pragma unroll
    for (int i = 0; i < 4; i++) {
        int m0 = i * 32 + ty * 2;
#pragma unroll
        for (int j = 0; j < 8; j++) {
            int ncol = ntile + (j >> 1) * 32 + tx * 2 + (j & 1);
            float2 v = upk2(acc2[i][j]);
            outp[(size_t)m0 * HIDd + ncol]       = v.x;
            outp[(size_t)(m0 + 1) * HIDd + ncol] = v.y;
        }
    }
}

// ---------------- split-K reduce + bias + BN + ReLU ----------------
__global__ void k_bnrelu(const float* __restrict__ fb,
                         const float* __restrict__ g,
                         const float* __restrict__ beta) {
    int gid = blockIdx.x * 256 + threadIdx.x;
    float s = 0.f;
#pragma unroll
    for (int p = 0; p < SPLITK; p++) s += g_h1part[(size_t)p * (Bsz * HIDd) + gid];
    int o = gid & (HIDd - 1);
    float val = (s + fb[o]) * (g[o] * rsqrtf(1.f + 1e-5f)) + beta[o];
    g_h1[gid] = fmaxf(val, 0.f);
}

// ---------------- fc2 ----------------
__global__ void k_fc2(const float* __restrict__ w2, const float* __restrict__ b2,
                      float* __restrict__ out) {
    int b = blockIdx.x, tid = threadIdx.x;
    float a0 = 0.f, a1 = 0.f;
    for (int o = tid; o < HIDd; o += 256) {
        float h = g_h1[(size_t)b * HIDd + o];
        a0 += h * w2[o];
        a1 += h * w2[HIDd + o];
    }
    __shared__ float r0[256], r1[256];
    r0[tid] = a0; r1[tid] = a1;
    __syncthreads();
    for (int s = 128; s > 0; s >>= 1) {
        if (tid < s) { r0[tid] += r0[tid + s]; r1[tid] += r1[tid + s]; }
        __syncthreads();
    }
    if (tid == 0) {
        out[b * 2 + 0] = r0[0] + b2[0];
        out[b * 2 + 1] = r1[0] + b2[1];
    }
}

extern "C" void kernel_launch(void* const* d_in, const int* in_sizes, int n_in,
                              void* d_out, int out_size) {
    const float* x       = (const float*)d_in[0];
    const int*   ei      = (const int*)  d_in[1];
    const float* eattr   = (const float*)d_in[2];
    const float* tcn_w   = (const float*)d_in[3];
    const float* tcn_b   = (const float*)d_in[4];
    const float* lin_l_w = (const float*)d_in[5];
    const float* lin_l_b = (const float*)d_in[6];
    const float* lin_e_w = (const float*)d_in[7];
    const float* lin_e_b = (const float*)d_in[8];
    const float* att     = (const float*)d_in[9];
    const float* fc1_w   = (const float*)d_in[10];
    const float* fc1_b   = (const float*)d_in[11];
    const float* bn_g    = (const float*)d_in[12];
    const float* bn_b    = (const float*)d_in[13];
    const float* fc2_w   = (const float*)d_in[14];
    const float* fc2_b   = (const float*)d_in[15];
    float* out = (float*)d_out;

    k_csr<<<1, 512>>>(ei);
    k_tcn<<<dim3(4, Bsz), 128>>>(x, tcn_w, tcn_b);
    k_linl<<<dim3(2, Bsz), 256>>>(lin_l_w, lin_l_b);
    k_gat<<<dim3(NN, Bsz), 128>>>(eattr, lin_e_w, lin_e_b, att);
    k_fc1<<<dim3(16, SPLITK), 256>>>(fc1_w);
    k_bnrelu<<<(Bsz * HIDd) / 256, 256>>>(fc1_b, bn_g, bn_b);
    k_fc2<<<Bsz, 256>>>(fc2_w, fc2_b, out);
}

// round 6
// speedup vs baseline: 1.5180x; 1.5180x over previous
#include <cuda_runtime.h>
#include <cuda_bf16.h>
#include <math.h>
#include <stdint.h>

#define Bsz   128
#define Wd    128
#define FIN   64
#define NN    64
#define EE    4096
#define EDd   16
#define HC    128
#define FLATd 8192
#define HIDd  2048
#define SPLITK 16
#define CHUNK 128

// ---------------- scratch ----------------
__device__ __align__(128) float g_xg[Bsz * NN * Wd];
__device__ __align__(128) float g_h[Bsz * NN * HC];
__device__ __align__(128) float g_xflat[Bsz * FLATd];
__device__ __align__(128) float g_h1part[SPLITK * Bsz * HIDd];
__device__ __align__(128) float g_h1[Bsz * HIDd];
__device__ int  g_csr_off[NN + 1];
__device__ int2 g_csr_es[EE];

// ---------------- helpers ----------------
__device__ __forceinline__ uint32_t smem_u32(const void* p) {
    uint32_t a;
    asm("{ .reg .u64 t; cvta.to.shared.u64 t, %1; cvt.u32.u64 %0, t; }" : "=r"(a) : "l"(p));
    return a;
}
__device__ __forceinline__ void ldm_x4(uint32_t (&r)[4], uint32_t addr) {
    asm volatile("ldmatrix.sync.aligned.m8n8.x4.shared.b16 {%0,%1,%2,%3}, [%4];"
        : "=r"(r[0]), "=r"(r[1]), "=r"(r[2]), "=r"(r[3]) : "r"(addr));
}
__device__ __forceinline__ void mma_bf16(float (&d)[4], const uint32_t (&a)[4],
                                         uint32_t b0, uint32_t b1) {
    asm volatile(
        "mma.sync.aligned.m16n8k16.row.col.f32.bf16.bf16.f32 "
        "{%0,%1,%2,%3}, {%4,%5,%6,%7}, {%8,%9}, {%0,%1,%2,%3};"
        : "+f"(d[0]), "+f"(d[1]), "+f"(d[2]), "+f"(d[3])
        : "r"(a[0]), "r"(a[1]), "r"(a[2]), "r"(a[3]), "r"(b0), "r"(b1));
}
__device__ __forceinline__ void cvtpair(float a, float b, uint32_t& hi, uint32_t& lo) {
    __nv_bfloat16 ha = __float2bfloat16(a), hb2 = __float2bfloat16(b);
    float ra = a - __bfloat162float(ha), rb = b - __bfloat162float(hb2);
    __nv_bfloat16 la = __float2bfloat16(ra), lb = __float2bfloat16(rb);
    hi = (uint32_t)__bfloat16_as_ushort(ha) | ((uint32_t)__bfloat16_as_ushort(hb2) << 16);
    lo = (uint32_t)__bfloat16_as_ushort(la) | ((uint32_t)__bfloat16_as_ushort(lb) << 16);
}
__device__ __forceinline__ void sts_v2(uint32_t addr, uint32_t x, uint32_t y) {
    asm volatile("st.shared.v2.b32 [%0], {%1,%2};" :: "r"(addr), "r"(x), "r"(y) : "memory");
}

// ---------------- CSR build ----------------
__global__ void k_csr(const int* __restrict__ ei) {
    __shared__ int cnt[NN];
    __shared__ int off[NN + 1];
    __shared__ int cur[NN];
    int tid = threadIdx.x;
    if (tid < NN) cnt[tid] = 0;
    __syncthreads();
    for (int e = tid; e < EE; e += blockDim.x)
        atomicAdd(&cnt[ei[EE + e]], 1);
    __syncthreads();
    if (tid == 0) {
        int run = 0;
        for (int k = 0; k < NN; k++) { off[k] = run; cur[k] = run; run += cnt[k]; }
        off[NN] = run;
    }
    __syncthreads();
    for (int e = tid; e < EE; e += blockDim.x) {
        int d = ei[EE + e];
        int pos = atomicAdd(&cur[d], 1);
        g_csr_es[pos] = make_int2(e, ei[e]);
    }
    if (tid <= NN) g_csr_off[tid] = off[tid];
}

// ---------------- TCN conv1d(k=3,pad=1) ----------------
__global__ void k_tcn(const float* __restrict__ x,
                      const float* __restrict__ tw,
                      const float* __restrict__ tb) {
    __shared__ float xs[FIN * 129];
    __shared__ float sw[16 * 192];
    int b = blockIdx.y, nc = blockIdx.x;
    int tid = threadIdx.x;
    const float* xb = x + (size_t)b * Wd * FIN;
    for (int idx = tid; idx < Wd * FIN; idx += 128) {
        int w = idx >> 6, i = idx & 63;
        xs[i * 129 + w] = xb[idx];
    }
    for (int idx = tid; idx < 16 * 192; idx += 128)
        sw[idx] = tw[nc * 16 * 192 + idx];
    __syncthreads();
    int w = tid;
    float acc[16];
#pragma unroll
    for (int nl = 0; nl < 16; nl++) acc[nl] = tb[nc * 16 + nl];
    for (int i = 0; i < FIN; i++) {
        float x0 = xs[i * 129 + w];
        float xm = (w > 0)   ? xs[i * 129 + w - 1] : 0.f;
        float xp = (w < 127) ? xs[i * 129 + w + 1] : 0.f;
#pragma unroll
        for (int nl = 0; nl < 16; nl++) {
            const float* wp = &sw[nl * 192 + i * 3];
            acc[nl] += xm * wp[0] + x0 * wp[1] + xp * wp[2];
        }
    }
#pragma unroll
    for (int nl = 0; nl < 16; nl++)
        g_xg[((size_t)b * NN + nc * 16 + nl) * Wd + w] = acc[nl];
}

// ---------------- lin_l projection ----------------
__global__ void k_linl(const float* __restrict__ lw, const float* __restrict__ lb) {
    __shared__ float xs[NN * 129];
    __shared__ float ws[64 * 33];
    int b = blockIdx.y, oc = blockIdx.x;
    int tid = threadIdx.x;
    for (int idx = tid; idx < NN * Wd; idx += 256) {
        int n = idx >> 7, w = idx & 127;
        xs[n * 129 + w] = g_xg[(size_t)b * NN * Wd + idx];
    }
    int tx = tid & 15, ty = tid >> 4;
    float acc[4][4];
#pragma unroll
    for (int i = 0; i < 4; i++)
#pragma unroll
        for (int j = 0; j < 4; j++) acc[i][j] = 0.f;
    for (int wc = 0; wc < 4; wc++) {
        __syncthreads();
        for (int idx = tid; idx < 64 * 32; idx += 256) {
            int ol = idx >> 5, wl = idx & 31;
            ws[ol * 33 + wl] = lw[(oc * 64 + ol) * Wd + wc * 32 + wl];
        }
        __syncthreads();
#pragma unroll 4
        for (int wl = 0; wl < 32; wl++) {
            float a[4], bb[4];
#pragma unroll
            for (int j = 0; j < 4; j++) a[j]  = xs[(ty * 4 + j) * 129 + wc * 32 + wl];
#pragma unroll
            for (int j = 0; j < 4; j++) bb[j] = ws[(tx * 4 + j) * 33 + wl];
#pragma unroll
            for (int i = 0; i < 4; i++)
#pragma unroll
                for (int j = 0; j < 4; j++) acc[i][j] += a[i] * bb[j];
        }
    }
#pragma unroll
    for (int i = 0; i < 4; i++)
#pragma unroll
        for (int j = 0; j < 4; j++) {
            int n = ty * 4 + i, o = oc * 64 + tx * 4 + j;
            g_h[((size_t)b * NN + n) * HC + o] = acc[i][j] + lb[o];
        }
}

// ---------------- GAT: chunked deferred softmax (R3 version) ----------------
__global__ void __launch_bounds__(128) k_gat(const float* __restrict__ eattr,
                      const float* __restrict__ lew,
                      const float* __restrict__ leb,
                      const float* __restrict__ att) {
    __shared__ float4 ea_s[CHUNK * 4];
    __shared__ int2   es_s[CHUNK];
    int n = blockIdx.x, b = blockIdx.y;
    int t = threadIdx.x;
    int lane = t & 31;
    const float4* w4 = (const float4*)(lew + t * EDd);
    float4 w0 = w4[0], w1 = w4[1], w2 = w4[2], w3 = w4[3];
    float eb = leb[t];
    float att_t = att[t];
    const float* hb = g_h + (size_t)b * NN * HC;
    float hd = hb[n * HC + t];

    int beg = g_csr_off[n], end = g_csr_off[n + 1];
    int deg = end - beg;
    const int2* lst = g_csr_es + beg;
    const float4* eab = (const float4*)eattr + (size_t)b * EE * 4;

    float m = -1e30f, den = 0.f, acc = 0.f;

    for (int base = 0; base < deg; base += CHUNK) {
        int cnt = min(CHUNK, deg - base);
        if (t < cnt) es_s[t] = lst[base + t];
        __syncthreads();
        for (int idx = t; idx < cnt * 4; idx += 128)
            ea_s[idx] = eab[(size_t)es_s[idx >> 2].x * 4 + (idx & 3)];
        __syncthreads();

        float sr[4] = {-1e30f, -1e30f, -1e30f, -1e30f};
#pragma unroll
        for (int q = 0; q < 4; q++) {
            int lim = min(32, cnt - q * 32);
            float sq = -1e30f;
            for (int jj = 0; jj < lim; jj++) {
                int j = q * 32 + jj;
                int2 p = es_s[j];
                float4 q0 = ea_s[j * 4 + 0];
                float4 q1 = ea_s[j * 4 + 1];
                float4 q2 = ea_s[j * 4 + 2];
                float4 q3 = ea_s[j * 4 + 3];
                float hs = hb[p.y * HC + t];
                float ev = eb
                    + q0.x * w0.x + q0.y * w0.y + q0.z * w0.z + q0.w * w0.w
                    + q1.x * w1.x + q1.y * w1.y + q1.z * w1.z + q1.w * w1.w
                    + q2.x * w2.x + q2.y * w2.y + q2.z * w2.z + q2.w * w2.w
                    + q3.x * w3.x + q3.y * w3.y + q3.z * w3.z + q3.w * w3.w;
                float z = hd + hs + ev;
                float xv = fmaxf(z, 0.01f * z) * att_t;
                xv += __shfl_xor_sync(0xffffffffu, xv, 16);
                xv += __shfl_xor_sync(0xffffffffu, xv, 8);
                xv += __shfl_xor_sync(0xffffffffu, xv, 4);
                xv += __shfl_xor_sync(0xffffffffu, xv, 2);
                xv += __shfl_xor_sync(0xffffffffu, xv, 1);
                if (jj == lane) sq = xv;
            }
            sr[q] = sq;
        }

        float cm = fmaxf(fmaxf(sr[0], sr[1]), fmaxf(sr[2], sr[3]));
        cm = fmaxf(cm, __shfl_xor_sync(0xffffffffu, cm, 16));
        cm = fmaxf(cm, __shfl_xor_sync(0xffffffffu, cm, 8));
        cm = fmaxf(cm, __shfl_xor_sync(0xffffffffu, cm, 4));
        cm = fmaxf(cm, __shfl_xor_sync(0xffffffffu, cm, 2));
        cm = fmaxf(cm, __shfl_xor_sync(0xffffffffu, cm, 1));
        float mnew = fmaxf(m, cm);
        float resc = __expf(m - mnew);
        den *= resc; acc *= resc;
        m = mnew;
        float wr[4];
#pragma unroll
        for (int q = 0; q < 4; q++) wr[q] = __expf(sr[q] - m);
        float dl = wr[0] + wr[1] + wr[2] + wr[3];
        dl += __shfl_xor_sync(0xffffffffu, dl, 16);
        dl += __shfl_xor_sync(0xffffffffu, dl, 8);
        dl += __shfl_xor_sync(0xffffffffu, dl, 4);
        dl += __shfl_xor_sync(0xffffffffu, dl, 2);
        dl += __shfl_xor_sync(0xffffffffu, dl, 1);
        den += dl;

#pragma unroll
        for (int q = 0; q < 4; q++) {
            int lim = min(32, cnt - q * 32);
            for (int jj = 0; jj < lim; jj++) {
                float wj = __shfl_sync(0xffffffffu, wr[q], jj);
                int2 p = es_s[q * 32 + jj];
                float hs = hb[p.y * HC + t];
                acc += wj * hs;
            }
        }
        __syncthreads();
    }

    float v = acc / (den + 1e-16f);
    float o = (v > 0.f) ? v : expm1f(v);
    g_xflat[(size_t)b * FLATd + n * HC + t] = o;
}

// ---------------- fc1 via mma.sync bf16 3-split ----------------
// block: 128m x 64n, K=512 (splitK=16), 8 warps (warp tile 32x32), BK=32.
// smem rows padded to 40 bf16 (80B) -> conflict-free ldmatrix.
#define FA_HI 0
#define FA_LO 10240
#define FB_HI 20480
#define FB_LO 25600

__global__ void __launch_bounds__(256) k_fc1_mma(const float* __restrict__ wq) {
    __shared__ __align__(16) unsigned char smbuf[30720];
    const uint32_t sb = smem_u32(smbuf);
    const int tid = threadIdx.x;
    const int wid = tid >> 5, lane = tid & 31;
    const int wm = wid & 3, wn = wid >> 2;
    const int ntile = blockIdx.x << 6;          // 32 n-tiles of 64
    const int k0 = blockIdx.y << 9;             // 16 splits of 512

    float acc[2][4][4];
#pragma unroll
    for (int a = 0; a < 2; a++)
#pragma unroll
        for (int b = 0; b < 4; b++)
#pragma unroll
            for (int c = 0; c < 4; c++) acc[a][b][c] = 0.f;

    // ldmatrix base addresses
    const uint32_t aAddrBase = sb + (uint32_t)((wm * 32 + (lane & 15)) * 80
                               + ((lane >> 4) & 1) * 16);
    const uint32_t bAddrBase = sb + (uint32_t)((wn * 32 + (lane & 7) + ((lane >> 4) ? 8 : 0)) * 80
                               + ((lane >> 3) & 1) * 16);

    // prefetch regs
    float4 fA[4], fB[2];
#pragma unroll
    for (int r = 0; r < 4; r++) {
        int i = tid + r * 256;
        fA[r] = *(const float4*)(g_xflat + (size_t)(i >> 3) * FLATd + k0 + (i & 7) * 4);
    }
#pragma unroll
    for (int r = 0; r < 2; r++) {
        int i = tid + r * 256;
        fB[r] = *(const float4*)(wq + (size_t)(ntile + (i >> 3)) * FLATd + k0 + (i & 7) * 4);
    }

    for (int it = 0; it < 16; it++) {
        // convert + store to smem
#pragma unroll
        for (int r = 0; r < 4; r++) {
            int i = tid + r * 256;
            uint32_t addr = (uint32_t)((i >> 3) * 80 + (i & 7) * 8);
            uint32_t h0, l0, h1, l1;
            cvtpair(fA[r].x, fA[r].y, h0, l0);
            cvtpair(fA[r].z, fA[r].w, h1, l1);
            sts_v2(sb + FA_HI + addr, h0, h1);
            sts_v2(sb + FA_LO + addr, l0, l1);
        }
#pragma unroll
        for (int r = 0; r < 2; r++) {
            int i = tid + r * 256;
            uint32_t addr = (uint32_t)((i >> 3) * 80 + (i & 7) * 8);
            uint32_t h0, l0, h1, l1;
            cvtpair(fB[r].x, fB[r].y, h0, l0);
            cvtpair(fB[r].z, fB[r].w, h1, l1);
            sts_v2(sb + FB_HI + addr, h0, h1);
            sts_v2(sb + FB_LO + addr, l0, l1);
        }
        __syncthreads();

        if (it < 15) {   // prefetch next chunk while computing
            int knext = k0 + (it + 1) * 32;
#pragma unroll
            for (int r = 0; r < 4; r++) {
                int i = tid + r * 256;
                fA[r] = *(const float4*)(g_xflat + (size_t)(i >> 3) * FLATd + knext + (i & 7) * 4);
            }
#pragma unroll
            for (int r = 0; r < 2; r++) {
                int i = tid + r * 256;
                fB[r] = *(const float4*)(wq + (size_t)(ntile + (i >> 3)) * FLATd + knext + (i & 7) * 4);
            }
        }

#pragma unroll
        for (int ks = 0; ks < 2; ks++) {
            uint32_t Ah[2][4], Al[2][4], Bh[2][4], Bl[2][4];
#pragma unroll
            for (int mt = 0; mt < 2; mt++) {
                uint32_t a = aAddrBase + (uint32_t)(mt * 16 * 80 + ks * 32);
                ldm_x4(Ah[mt], a + FA_HI);
                ldm_x4(Al[mt], a + FA_LO);
            }
#pragma unroll
            for (int np = 0; np < 2; np++) {
                uint32_t a = bAddrBase + (uint32_t)(np * 16 * 80 + ks * 32);
                ldm_x4(Bh[np], a + FB_HI);
                ldm_x4(Bl[np], a + FB_LO);
            }
#pragma unroll
            for (int mt = 0; mt < 2; mt++)
#pragma unroll
                for (int np = 0; np < 2; np++)
#pragma unroll
                    for (int hf = 0; hf < 2; hf++) {
                        int nt = np * 2 + hf;
                        mma_bf16(acc[mt][nt], Ah[mt], Bh[np][hf * 2], Bh[np][hf * 2 + 1]);
                        mma_bf16(acc[mt][nt], Ah[mt], Bl[np][hf * 2], Bl[np][hf * 2 + 1]);
                        mma_bf16(acc[mt][nt], Al[mt], Bh[np][hf * 2], Bh[np][hf * 2 + 1]);
                    }
        }
        __syncthreads();
    }

    float* outp = g_h1part + (size_t)blockIdx.y * (Bsz * HIDd);
#pragma unroll
    for (int mt = 0; mt < 2; mt++) {
        int rrow = wm * 32 + mt * 16 + (lane >> 2);
#pragma unroll
        for (int nt = 0; nt < 4; nt++) {
            int ccol = ntile + wn * 32 + nt * 8 + (lane & 3) * 2;
            *(float2*)&outp[(size_t)rrow * HIDd + ccol] =
                make_float2(acc[mt][nt][0], acc[mt][nt][1]);
            *(float2*)&outp[(size_t)(rrow + 8) * HIDd + ccol] =
                make_float2(acc[mt][nt][2], acc[mt][nt][3]);
        }
    }
}

// ---------------- split-K reduce + bias + BN + ReLU ----------------
__global__ void k_bnrelu(const float* __restrict__ fb,
                         const float* __restrict__ g,
                         const float* __restrict__ beta) {
    int gid = blockIdx.x * 256 + threadIdx.x;
    float s = 0.f;
#pragma unroll
    for (int p = 0; p < SPLITK; p++) s += g_h1part[(size_t)p * (Bsz * HIDd) + gid];
    int o = gid & (HIDd - 1);
    float val = (s + fb[o]) * (g[o] * rsqrtf(1.f + 1e-5f)) + beta[o];
    g_h1[gid] = fmaxf(val, 0.f);
}

// ---------------- fc2 ----------------
__global__ void k_fc2(const float* __restrict__ w2, const float* __restrict__ b2,
                      float* __restrict__ out) {
    int b = blockIdx.x, tid = threadIdx.x;
    float a0 = 0.f, a1 = 0.f;
    for (int o = tid; o < HIDd; o += 256) {
        float h = g_h1[(size_t)b * HIDd + o];
        a0 += h * w2[o];
        a1 += h * w2[HIDd + o];
    }
    __shared__ float r0[256], r1[256];
    r0[tid] = a0; r1[tid] = a1;
    __syncthreads();
    for (int s = 128; s > 0; s >>= 1) {
        if (tid < s) { r0[tid] += r0[tid + s]; r1[tid] += r1[tid + s]; }
        __syncthreads();
    }
    if (tid == 0) {
        out[b * 2 + 0] = r0[0] + b2[0];
        out[b * 2 + 1] = r1[0] + b2[1];
    }
}

extern "C" void kernel_launch(void* const* d_in, const int* in_sizes, int n_in,
                              void* d_out, int out_size) {
    const float* x       = (const float*)d_in[0];
    const int*   ei      = (const int*)  d_in[1];
    const float* eattr   = (const float*)d_in[2];
    const float* tcn_w   = (const float*)d_in[3];
    const float* tcn_b   = (const float*)d_in[4];
    const float* lin_l_w = (const float*)d_in[5];
    const float* lin_l_b = (const float*)d_in[6];
    const float* lin_e_w = (const float*)d_in[7];
    const float* lin_e_b = (const float*)d_in[8];
    const float* att     = (const float*)d_in[9];
    const float* fc1_w   = (const float*)d_in[10];
    const float* fc1_b   = (const float*)d_in[11];
    const float* bn_g    = (const float*)d_in[12];
    const float* bn_b    = (const float*)d_in[13];
    const float* fc2_w   = (const float*)d_in[14];
    const float* fc2_b   = (const float*)d_in[15];
    float* out = (float*)d_out;

    k_csr<<<1, 512>>>(ei);
    k_tcn<<<dim3(4, Bsz), 128>>>(x, tcn_w, tcn_b);
    k_linl<<<dim3(2, Bsz), 256>>>(lin_l_w, lin_l_b);
    k_gat<<<dim3(NN, Bsz), 128>>>(eattr, lin_e_w, lin_e_b, att);
    k_fc1_mma<<<dim3(32, SPLITK), 256>>>(fc1_w);
    k_bnrelu<<<(Bsz * HIDd) / 256, 256>>>(fc1_b, bn_g, bn_b);
    k_fc2<<<Bsz, 256>>>(fc2_w, fc2_b, out);
}

// round 7
// speedup vs baseline: 1.5254x; 1.0049x over previous
#include <cuda_runtime.h>
#include <cuda_bf16.h>
#include <math.h>
#include <stdint.h>

#define Bsz   128
#define Wd    128
#define FIN   64
#define NN    64
#define EE    4096
#define EDd   16
#define HC    128
#define FLATd 8192
#define HIDd  2048
#define SPLITK 16
#define CHUNK 128

// ---------------- scratch ----------------
__device__ __align__(128) float g_xg[Bsz * NN * Wd];
__device__ __align__(128) float g_h[Bsz * NN * HC];
__device__ __align__(128) float g_xflat[Bsz * FLATd];
__device__ __align__(128) float g_h1part[SPLITK * Bsz * HIDd];
__device__ __align__(128) float g_h1[Bsz * HIDd];
__device__ int  g_csr_off[NN + 1];
__device__ int2 g_csr_es[EE];

// ---------------- helpers ----------------
__device__ __forceinline__ uint32_t smem_u32(const void* p) {
    uint32_t a;
    asm("{ .reg .u64 t; cvta.to.shared.u64 t, %1; cvt.u32.u64 %0, t; }" : "=r"(a) : "l"(p));
    return a;
}
__device__ __forceinline__ void ldm_x4(uint32_t (&r)[4], uint32_t addr) {
    asm volatile("ldmatrix.sync.aligned.m8n8.x4.shared.b16 {%0,%1,%2,%3}, [%4];"
        : "=r"(r[0]), "=r"(r[1]), "=r"(r[2]), "=r"(r[3]) : "r"(addr));
}
__device__ __forceinline__ void mma_bf16(float (&d)[4], const uint32_t (&a)[4],
                                         uint32_t b0, uint32_t b1) {
    asm volatile(
        "mma.sync.aligned.m16n8k16.row.col.f32.bf16.bf16.f32 "
        "{%0,%1,%2,%3}, {%4,%5,%6,%7}, {%8,%9}, {%0,%1,%2,%3};"
        : "+f"(d[0]), "+f"(d[1]), "+f"(d[2]), "+f"(d[3])
        : "r"(a[0]), "r"(a[1]), "r"(a[2]), "r"(a[3]), "r"(b0), "r"(b1));
}
__device__ __forceinline__ void cvtpair(float a, float b, uint32_t& hi, uint32_t& lo) {
    __nv_bfloat16 ha = __float2bfloat16(a), hb2 = __float2bfloat16(b);
    float ra = a - __bfloat162float(ha), rb = b - __bfloat162float(hb2);
    __nv_bfloat16 la = __float2bfloat16(ra), lb = __float2bfloat16(rb);
    hi = (uint32_t)__bfloat16_as_ushort(ha) | ((uint32_t)__bfloat16_as_ushort(hb2) << 16);
    lo = (uint32_t)__bfloat16_as_ushort(la) | ((uint32_t)__bfloat16_as_ushort(lb) << 16);
}
__device__ __forceinline__ void sts_v2(uint32_t addr, uint32_t x, uint32_t y) {
    asm volatile("st.shared.v2.b32 [%0], {%1,%2};" :: "r"(addr), "r"(x), "r"(y) : "memory");
}

// ---------------- CSR build ----------------
__global__ void k_csr(const int* __restrict__ ei) {
    __shared__ int cnt[NN];
    __shared__ int off[NN + 1];
    __shared__ int cur[NN];
    int tid = threadIdx.x;
    if (tid < NN) cnt[tid] = 0;
    __syncthreads();
    for (int e = tid; e < EE; e += blockDim.x)
        atomicAdd(&cnt[ei[EE + e]], 1);
    __syncthreads();
    if (tid == 0) {
        int run = 0;
        for (int k = 0; k < NN; k++) { off[k] = run; cur[k] = run; run += cnt[k]; }
        off[NN] = run;
    }
    __syncthreads();
    for (int e = tid; e < EE; e += blockDim.x) {
        int d = ei[EE + e];
        int pos = atomicAdd(&cur[d], 1);
        g_csr_es[pos] = make_int2(e, ei[e]);
    }
    if (tid <= NN) g_csr_off[tid] = off[tid];
}

// ---------------- TCN conv1d(k=3,pad=1) ----------------
__global__ void k_tcn(const float* __restrict__ x,
                      const float* __restrict__ tw,
                      const float* __restrict__ tb) {
    __shared__ float xs[FIN * 129];
    __shared__ float sw[16 * 192];
    int b = blockIdx.y, nc = blockIdx.x;
    int tid = threadIdx.x;
    const float* xb = x + (size_t)b * Wd * FIN;
    for (int idx = tid; idx < Wd * FIN; idx += 128) {
        int w = idx >> 6, i = idx & 63;
        xs[i * 129 + w] = xb[idx];
    }
    for (int idx = tid; idx < 16 * 192; idx += 128)
        sw[idx] = tw[nc * 16 * 192 + idx];
    __syncthreads();
    int w = tid;
    float acc[16];
#pragma unroll
    for (int nl = 0; nl < 16; nl++) acc[nl] = tb[nc * 16 + nl];
    for (int i = 0; i < FIN; i++) {
        float x0 = xs[i * 129 + w];
        float xm = (w > 0)   ? xs[i * 129 + w - 1] : 0.f;
        float xp = (w < 127) ? xs[i * 129 + w + 1] : 0.f;
#pragma unroll
        for (int nl = 0; nl < 16; nl++) {
            const float* wp = &sw[nl * 192 + i * 3];
            acc[nl] += xm * wp[0] + x0 * wp[1] + xp * wp[2];
        }
    }
#pragma unroll
    for (int nl = 0; nl < 16; nl++)
        g_xg[((size_t)b * NN + nc * 16 + nl) * Wd + w] = acc[nl];
}

// ---------------- lin_l projection ----------------
__global__ void k_linl(const float* __restrict__ lw, const float* __restrict__ lb) {
    __shared__ float xs[NN * 129];
    __shared__ float ws[64 * 33];
    int b = blockIdx.y, oc = blockIdx.x;
    int tid = threadIdx.x;
    for (int idx = tid; idx < NN * Wd; idx += 256) {
        int n = idx >> 7, w = idx & 127;
        xs[n * 129 + w] = g_xg[(size_t)b * NN * Wd + idx];
    }
    int tx = tid & 15, ty = tid >> 4;
    float acc[4][4];
#pragma unroll
    for (int i = 0; i < 4; i++)
#pragma unroll
        for (int j = 0; j < 4; j++) acc[i][j] = 0.f;
    for (int wc = 0; wc < 4; wc++) {
        __syncthreads();
        for (int idx = tid; idx < 64 * 32; idx += 256) {
            int ol = idx >> 5, wl = idx & 31;
            ws[ol * 33 + wl] = lw[(oc * 64 + ol) * Wd + wc * 32 + wl];
        }
        __syncthreads();
#pragma unroll 4
        for (int wl = 0; wl < 32; wl++) {
            float a[4], bb[4];
#pragma unroll
            for (int j = 0; j < 4; j++) a[j]  = xs[(ty * 4 + j) * 129 + wc * 32 + wl];
#pragma unroll
            for (int j = 0; j < 4; j++) bb[j] = ws[(tx * 4 + j) * 33 + wl];
#pragma unroll
            for (int i = 0; i < 4; i++)
#pragma unroll
                for (int j = 0; j < 4; j++) acc[i][j] += a[i] * bb[j];
        }
    }
#pragma unroll
    for (int i = 0; i < 4; i++)
#pragma unroll
        for (int j = 0; j < 4; j++) {
            int n = ty * 4 + i, o = oc * 64 + tx * 4 + j;
            g_h[((size_t)b * NN + n) * HC + o] = acc[i][j] + lb[o];
        }
}

// ---------------- GAT: chunked softmax, smem-transposed score reduction ----------------
__global__ void __launch_bounds__(128) k_gat(const float* __restrict__ eattr,
                      const float* __restrict__ lew,
                      const float* __restrict__ leb,
                      const float* __restrict__ att) {
    __shared__ float4 ea_s[CHUNK * 4];        // 8 KB
    __shared__ int2   es_s[CHUNK];            // 1 KB
    __shared__ float  p_s[4 * 32 * 33];       // 16.9 KB: [head][edge-in-window][chan pad33]
    int n = blockIdx.x, b = blockIdx.y;
    int t = threadIdx.x;
    int lane = t & 31, h = t >> 5;
    const float4* w4 = (const float4*)(lew + t * EDd);
    float4 w0 = w4[0], w1 = w4[1], w2 = w4[2], w3 = w4[3];
    float eb = leb[t];
    float att_t = att[t];
    const float* hb = g_h + (size_t)b * NN * HC;
    float hd = hb[n * HC + t];

    int beg = g_csr_off[n], end = g_csr_off[n + 1];
    int deg = end - beg;
    const int2* lst = g_csr_es + beg;
    const float4* eab = (const float4*)eattr + (size_t)b * EE * 4;

    float* prow = &p_s[h * (32 * 33)];

    float m = -1e30f, den = 0.f, acc = 0.f;

    for (int base = 0; base < deg; base += CHUNK) {
        int cnt = min(CHUNK, deg - base);
        if (t < cnt) es_s[t] = lst[base + t];
        __syncthreads();
        for (int idx = t; idx < cnt * 4; idx += 128)
            ea_s[idx] = eab[(size_t)es_s[idx >> 2].x * 4 + (idx & 3)];
        __syncthreads();

        float sr[4];
#pragma unroll
        for (int q = 0; q < 4; q++) {
            int win = q * 32;
            int lim = min(32, cnt - win);
            // compute products for this 32-edge window, park in p_s
            for (int jj = 0; jj < lim; jj++) {
                int j = win + jj;
                int2 p = es_s[j];
                float4 q0 = ea_s[j * 4 + 0];
                float4 q1 = ea_s[j * 4 + 1];
                float4 q2 = ea_s[j * 4 + 2];
                float4 q3 = ea_s[j * 4 + 3];
                float hs = hb[p.y * HC + t];
                float ev = eb
                    + q0.x * w0.x + q0.y * w0.y + q0.z * w0.z + q0.w * w0.w
                    + q1.x * w1.x + q1.y * w1.y + q1.z * w1.z + q1.w * w1.w
                    + q2.x * w2.x + q2.y * w2.y + q2.z * w2.z + q2.w * w2.w
                    + q3.x * w3.x + q3.y * w3.y + q3.z * w3.z + q3.w * w3.w;
                float z = hd + hs + ev;
                prow[jj * 33 + lane] = fmaxf(z, 0.01f * z) * att_t;
            }
            __syncwarp();
            // transposed reduce: lane sums edge (win+lane)'s 32 channel products
            float sq = -1e30f;
            if (lane < lim) {
                const float* rp = &prow[lane * 33];
                float s0 = 0.f, s1 = 0.f, s2 = 0.f, s3 = 0.f;
#pragma unroll
                for (int c4 = 0; c4 < 8; c4++) {
                    s0 += rp[c4 * 4 + 0];
                    s1 += rp[c4 * 4 + 1];
                    s2 += rp[c4 * 4 + 2];
                    s3 += rp[c4 * 4 + 3];
                }
                sq = (s0 + s1) + (s2 + s3);
            }
            sr[q] = sq;
            __syncwarp();
        }

        // ---- pass 2: chunk max / weights / denom ----
        float cm = fmaxf(fmaxf(sr[0], sr[1]), fmaxf(sr[2], sr[3]));
        cm = fmaxf(cm, __shfl_xor_sync(0xffffffffu, cm, 16));
        cm = fmaxf(cm, __shfl_xor_sync(0xffffffffu, cm, 8));
        cm = fmaxf(cm, __shfl_xor_sync(0xffffffffu, cm, 4));
        cm = fmaxf(cm, __shfl_xor_sync(0xffffffffu, cm, 2));
        cm = fmaxf(cm, __shfl_xor_sync(0xffffffffu, cm, 1));
        float mnew = fmaxf(m, cm);
        float resc = __expf(m - mnew);
        den *= resc; acc *= resc;
        m = mnew;
        float wr[4];
#pragma unroll
        for (int q = 0; q < 4; q++) wr[q] = __expf(sr[q] - m);
        float dl = wr[0] + wr[1] + wr[2] + wr[3];
        dl += __shfl_xor_sync(0xffffffffu, dl, 16);
        dl += __shfl_xor_sync(0xffffffffu, dl, 8);
        dl += __shfl_xor_sync(0xffffffffu, dl, 4);
        dl += __shfl_xor_sync(0xffffffffu, dl, 2);
        dl += __shfl_xor_sync(0xffffffffu, dl, 1);
        den += dl;

        // ---- pass 3: aggregation ----
#pragma unroll
        for (int q = 0; q < 4; q++) {
            int lim = min(32, cnt - q * 32);
            for (int jj = 0; jj < lim; jj++) {
                float wj = __shfl_sync(0xffffffffu, wr[q], jj);
                int2 p = es_s[q * 32 + jj];
                float hs = hb[p.y * HC + t];
                acc += wj * hs;
            }
        }
        __syncthreads();
    }

    float v = acc / (den + 1e-16f);
    float o = (v > 0.f) ? v : expm1f(v);
    g_xflat[(size_t)b * FLATd + n * HC + t] = o;
}

// ---------------- fc1 via mma.sync bf16 3-split ----------------
#define FA_HI 0
#define FA_LO 10240
#define FB_HI 20480
#define FB_LO 25600

__global__ void __launch_bounds__(256) k_fc1_mma(const float* __restrict__ wq) {
    __shared__ __align__(16) unsigned char smbuf[30720];
    const uint32_t sb = smem_u32(smbuf);
    const int tid = threadIdx.x;
    const int wid = tid >> 5, lane = tid & 31;
    const int wm = wid & 3, wn = wid >> 2;
    const int ntile = blockIdx.x << 6;
    const int k0 = blockIdx.y << 9;

    float acc[2][4][4];
#pragma unroll
    for (int a = 0; a < 2; a++)
#pragma unroll
        for (int b = 0; b < 4; b++)
#pragma unroll
            for (int c = 0; c < 4; c++) acc[a][b][c] = 0.f;

    const uint32_t aAddrBase = sb + (uint32_t)((wm * 32 + (lane & 15)) * 80
                               + ((lane >> 4) & 1) * 16);
    const uint32_t bAddrBase = sb + (uint32_t)((wn * 32 + (lane & 7) + ((lane >> 4) ? 8 : 0)) * 80
                               + ((lane >> 3) & 1) * 16);

    float4 fA[4], fB[2];
#pragma unroll
    for (int r = 0; r < 4; r++) {
        int i = tid + r * 256;
        fA[r] = *(const float4*)(g_xflat + (size_t)(i >> 3) * FLATd + k0 + (i & 7) * 4);
    }
#pragma unroll
    for (int r = 0; r < 2; r++) {
        int i = tid + r * 256;
        fB[r] = *(const float4*)(wq + (size_t)(ntile + (i >> 3)) * FLATd + k0 + (i & 7) * 4);
    }

    for (int it = 0; it < 16; it++) {
#pragma unroll
        for (int r = 0; r < 4; r++) {
            int i = tid + r * 256;
            uint32_t addr = (uint32_t)((i >> 3) * 80 + (i & 7) * 8);
            uint32_t h0, l0, h1, l1;
            cvtpair(fA[r].x, fA[r].y, h0, l0);
            cvtpair(fA[r].z, fA[r].w, h1, l1);
            sts_v2(sb + FA_HI + addr, h0, h1);
            sts_v2(sb + FA_LO + addr, l0, l1);
        }
#pragma unroll
        for (int r = 0; r < 2; r++) {
            int i = tid + r * 256;
            uint32_t addr = (uint32_t)((i >> 3) * 80 + (i & 7) * 8);
            uint32_t h0, l0, h1, l1;
            cvtpair(fB[r].x, fB[r].y, h0, l0);
            cvtpair(fB[r].z, fB[r].w, h1, l1);
            sts_v2(sb + FB_HI + addr, h0, h1);
            sts_v2(sb + FB_LO + addr, l0, l1);
        }
        __syncthreads();

        if (it < 15) {
            int knext = k0 + (it + 1) * 32;
#pragma unroll
            for (int r = 0; r < 4; r++) {
                int i = tid + r * 256;
                fA[r] = *(const float4*)(g_xflat + (size_t)(i >> 3) * FLATd + knext + (i & 7) * 4);
            }
#pragma unroll
            for (int r = 0; r < 2; r++) {
                int i = tid + r * 256;
                fB[r] = *(const float4*)(wq + (size_t)(ntile + (i >> 3)) * FLATd + knext + (i & 7) * 4);
            }
        }

#pragma unroll
        for (int ks = 0; ks < 2; ks++) {
            uint32_t Ah[2][4], Al[2][4], Bh[2][4], Bl[2][4];
#pragma unroll
            for (int mt = 0; mt < 2; mt++) {
                uint32_t a = aAddrBase + (uint32_t)(mt * 16 * 80 + ks * 32);
                ldm_x4(Ah[mt], a + FA_HI);
                ldm_x4(Al[mt], a + FA_LO);
            }
#pragma unroll
            for (int np = 0; np < 2; np++) {
                uint32_t a = bAddrBase + (uint32_t)(np * 16 * 80 + ks * 32);
                ldm_x4(Bh[np], a + FB_HI);
                ldm_x4(Bl[np], a + FB_LO);
            }
#pragma unroll
            for (int mt = 0; mt < 2; mt++)
#pragma unroll
                for (int np = 0; np < 2; np++)
#pragma unroll
                    for (int hf = 0; hf < 2; hf++) {
                        int nt = np * 2 + hf;
                        mma_bf16(acc[mt][nt], Ah[mt], Bh[np][hf * 2], Bh[np][hf * 2 + 1]);
                        mma_bf16(acc[mt][nt], Ah[mt], Bl[np][hf * 2], Bl[np][hf * 2 + 1]);
                        mma_bf16(acc[mt][nt], Al[mt], Bh[np][hf * 2], Bh[np][hf * 2 + 1]);
                    }
        }
        __syncthreads();
    }

    float* outp = g_h1part + (size_t)blockIdx.y * (Bsz * HIDd);
#pragma unroll
    for (int mt = 0; mt < 2; mt++) {
        int rrow = wm * 32 + mt * 16 + (lane >> 2);
#pragma unroll
        for (int nt = 0; nt < 4; nt++) {
            int ccol = ntile + wn * 32 + nt * 8 + (lane & 3) * 2;
            *(float2*)&outp[(size_t)rrow * HIDd + ccol] =
                make_float2(acc[mt][nt][0], acc[mt][nt][1]);
            *(float2*)&outp[(size_t)(rrow + 8) * HIDd + ccol] =
                make_float2(acc[mt][nt][2], acc[mt][nt][3]);
        }
    }
}

// ---------------- split-K reduce + bias + BN + ReLU ----------------
__global__ void k_bnrelu(const float* __restrict__ fb,
                         const float* __restrict__ g,
                         const float* __restrict__ beta) {
    int gid = blockIdx.x * 256 + threadIdx.x;
    float s = 0.f;
#pragma unroll
    for (int p = 0; p < SPLITK; p++) s += g_h1part[(size_t)p * (Bsz * HIDd) + gid];
    int o = gid & (HIDd - 1);
    float val = (s + fb[o]) * (g[o] * rsqrtf(1.f + 1e-5f)) + beta[o];
    g_h1[gid] = fmaxf(val, 0.f);
}

// ---------------- fc2 ----------------
__global__ void k_fc2(const float* __restrict__ w2, const float* __restrict__ b2,
                      float* __restrict__ out) {
    int b = blockIdx.x, tid = threadIdx.x;
    float a0 = 0.f, a1 = 0.f;
    for (int o = tid; o < HIDd; o += 256) {
        float h = g_h1[(size_t)b * HIDd + o];
        a0 += h * w2[o];
        a1 += h * w2[HIDd + o];
    }
    __shared__ float r0[256], r1[256];
    r0[tid] = a0; r1[tid] = a1;
    __syncthreads();
    for (int s = 128; s > 0; s >>= 1) {
        if (tid < s) { r0[tid] += r0[tid + s]; r1[tid] += r1[tid + s]; }
        __syncthreads();
    }
    if (tid == 0) {
        out[b * 2 + 0] = r0[0] + b2[0];
        out[b * 2 + 1] = r1[0] + b2[1];
    }
}

extern "C" void kernel_launch(void* const* d_in, const int* in_sizes, int n_in,
                              void* d_out, int out_size) {
    const float* x       = (const float*)d_in[0];
    const int*   ei      = (const int*)  d_in[1];
    const float* eattr   = (const float*)d_in[2];
    const float* tcn_w   = (const float*)d_in[3];
    const float* tcn_b   = (const float*)d_in[4];
    const float* lin_l_w = (const float*)d_in[5];
    const float* lin_l_b = (const float*)d_in[6];
    const float* lin_e_w = (const float*)d_in[7];
    const float* lin_e_b = (const float*)d_in[8];
    const float* att     = (const float*)d_in[9];
    const float* fc1_w   = (const float*)d_in[10];
    const float* fc1_b   = (const float*)d_in[11];
    const float* bn_g    = (const float*)d_in[12];
    const float* bn_b    = (const float*)d_in[13];
    const float* fc2_w   = (const float*)d_in[14];
    const float* fc2_b   = (const float*)d_in[15];
    float* out = (float*)d_out;

    k_csr<<<1, 512>>>(ei);
    k_tcn<<<dim3(4, Bsz), 128>>>(x, tcn_w, tcn_b);
    k_linl<<<dim3(2, Bsz), 256>>>(lin_l_w, lin_l_b);
    k_gat<<<dim3(NN, Bsz), 128>>>(eattr, lin_e_w, lin_e_b, att);
    k_fc1_mma<<<dim3(32, SPLITK), 256>>>(fc1_w);
    k_bnrelu<<<(Bsz * HIDd) / 256, 256>>>(fc1_b, bn_g, bn_b);
    k_fc2<<<Bsz, 256>>>(fc2_w, fc2_b, out);
}